// round 16
// baseline (speedup 1.0000x reference)
#include <cuda_runtime.h>
#include <math.h>
#include <stdint.h>

#define BB   64
#define SS   1024
#define DD   128
#define HH   256
#define M_ROWS (BB*SS)          // 65536
#define NPROJ  (4*HH)           // 1024
#define N2H    (2*HH)           // 512

typedef unsigned long long u64;

// ---------------- device scratch ----------------
__device__ __align__(16) float g_P[(size_t)M_ROWS * NPROJ];
__device__ __align__(16) float g_Hout[(size_t)M_ROWS * N2H];
__device__ __align__(16) float g_Wcat[DD * NPROJ];
__device__ __align__(16) float g_bcat[NPROJ];
__device__ __align__(16) float g_spart[4 * M_ROWS];
__device__ __align__(16) float g_attn[M_ROWS];
__device__ __align__(16) float g_cpart[8 * BB * N2H];

// ---------------- helpers ----------------
#define FMA2(d, a, b) asm("fma.rn.f32x2 %0, %1, %2, %0;" : "+l"(d) : "l"(a), "l"(b))
#define PACK2(d, lo, hi) asm("mov.b64 %0, {%1, %2};" : "=l"(d) : "f"(lo), "f"(hi))
#define UNPACK2(lo, hi, d) asm("mov.b64 {%0, %1}, %2;" : "=f"(lo), "=f"(hi) : "l"(d))

__device__ __forceinline__ float fast_sigmoid(float x) {
    return __fdividef(1.f, 1.f + __expf(-x));
}
__device__ __forceinline__ float fast_tanh(float x) {
    return 1.f - __fdividef(2.f, __expf(2.f * x) + 1.f);
}
__device__ __forceinline__ uint32_t to_tf32(float f) {
    uint32_t u;
    asm("cvt.rna.tf32.f32 %0, %1;" : "=r"(u) : "f"(f));
    return u;
}
__device__ __forceinline__ void mma_tf32(float* d, const uint32_t* a, const uint32_t* b) {
    asm volatile("mma.sync.aligned.m16n8k8.row.col.f32.tf32.tf32.f32 "
                 "{%0,%1,%2,%3}, {%4,%5,%6,%7}, {%8,%9}, {%0,%1,%2,%3};"
                 : "+f"(d[0]), "+f"(d[1]), "+f"(d[2]), "+f"(d[3])
                 : "r"(a[0]), "r"(a[1]), "r"(a[2]), "r"(a[3]), "r"(b[0]), "r"(b[1]));
}

// ---------------- weight packing ----------------
__global__ void pack_weights(const float* __restrict__ Wzf, const float* __restrict__ Whf,
                             const float* __restrict__ Wzb, const float* __restrict__ Whb,
                             const float* __restrict__ bzf, const float* __restrict__ bhf,
                             const float* __restrict__ bzb, const float* __restrict__ bhb) {
    int idx = blockIdx.x * 256 + threadIdx.x;
    if (idx < DD * NPROJ) {
        int k = idx >> 10;
        int n = idx & 1023;
        int sel = n >> 8;
        int c = n & 255;
        const float* W = (sel == 0) ? Wzf : (sel == 1) ? Whf : (sel == 2) ? Wzb : Whb;
        g_Wcat[idx] = W[k * HH + c];
    }
    if (idx < NPROJ) {
        int sel = idx >> 8;
        int c = idx & 255;
        const float* bp = (sel == 0) ? bzf : (sel == 1) ? bhf : (sel == 2) ? bzb : bhb;
        g_bcat[idx] = bp[c];
    }
}

// ---------------- tf32 tensor-core GEMM ----------------
// Row stride 136 words (136 mod 32 = 8): fragment-load banks = 8*tg + g, all 32
// lanes distinct -> conflict-free LDS for every af/bf load. (132 gave 4*tg+g with
// 2-3-way conflicts; the GEMM is fragment-LDS-bound, so this is the binding fix.)
// blockIdx.x = n-tile (fastest) for L2 A-reuse.
template<int K, int N, int MODE>
__device__ __forceinline__ void gemm_tc_body(const float* __restrict__ A, const float* __restrict__ B,
                                             const float* __restrict__ bias, float* __restrict__ C,
                                             const float* __restrict__ w2, float* __restrict__ spart) {
    __shared__ __align__(16) uint32_t As[16][136];
    __shared__ __align__(16) uint32_t Bs[16][136];
    __shared__ float red[128][9];

    const int tid = threadIdx.x;
    const int ntile = blockIdx.x;
    const int m0 = blockIdx.y * 128;
    const int n0 = ntile * 128;
    const int warp = tid >> 5;
    const int lane = tid & 31;
    const int wm = warp & 3;
    const int wn = warp >> 2;
    const int g  = lane >> 2;
    const int tg = lane & 3;

    const int arow = tid >> 2;
    const int akq  = (tid & 3) * 4;
    const int bkr  = tid >> 5;
    const int bnq  = (tid & 31) * 4;

    float acc[2][8][4];
#pragma unroll
    for (int mf = 0; mf < 2; ++mf)
#pragma unroll
        for (int nf = 0; nf < 8; ++nf)
#pragma unroll
            for (int q = 0; q < 4; ++q) acc[mf][nf][q] = 0.f;

    const int NC = K / 16;
    float4 a0s = *(const float4*)&A[(size_t)(m0 + arow) * K + akq];
    float4 a1s = *(const float4*)&A[(size_t)(m0 + arow + 64) * K + akq];
    float4 b0s = *(const float4*)&B[(size_t)bkr * N + n0 + bnq];
    float4 b1s = *(const float4*)&B[(size_t)(bkr + 8) * N + n0 + bnq];

    for (int c = 0; c < NC; ++c) {
        __syncthreads();
        As[akq + 0][arow] = to_tf32(a0s.x);
        As[akq + 1][arow] = to_tf32(a0s.y);
        As[akq + 2][arow] = to_tf32(a0s.z);
        As[akq + 3][arow] = to_tf32(a0s.w);
        As[akq + 0][arow + 64] = to_tf32(a1s.x);
        As[akq + 1][arow + 64] = to_tf32(a1s.y);
        As[akq + 2][arow + 64] = to_tf32(a1s.z);
        As[akq + 3][arow + 64] = to_tf32(a1s.w);
        {
            uint4 v0 = make_uint4(to_tf32(b0s.x), to_tf32(b0s.y), to_tf32(b0s.z), to_tf32(b0s.w));
            uint4 v1 = make_uint4(to_tf32(b1s.x), to_tf32(b1s.y), to_tf32(b1s.z), to_tf32(b1s.w));
            *(uint4*)&Bs[bkr][bnq] = v0;
            *(uint4*)&Bs[bkr + 8][bnq] = v1;
        }
        if (c + 1 < NC) {
            int kb = (c + 1) * 16;
            a0s = *(const float4*)&A[(size_t)(m0 + arow) * K + kb + akq];
            a1s = *(const float4*)&A[(size_t)(m0 + arow + 64) * K + kb + akq];
            b0s = *(const float4*)&B[(size_t)(kb + bkr) * N + n0 + bnq];
            b1s = *(const float4*)&B[(size_t)(kb + bkr + 8) * N + n0 + bnq];
        }
        __syncthreads();
#pragma unroll
        for (int kk = 0; kk < 16; kk += 8) {
            uint32_t af[2][4];
#pragma unroll
            for (int mf = 0; mf < 2; ++mf) {
                int mb = wm * 32 + mf * 16;
                af[mf][0] = As[kk + tg][mb + g];
                af[mf][1] = As[kk + tg][mb + g + 8];
                af[mf][2] = As[kk + tg + 4][mb + g];
                af[mf][3] = As[kk + tg + 4][mb + g + 8];
            }
            uint32_t bf[8][2];
#pragma unroll
            for (int nf = 0; nf < 8; ++nf) {
                int nb = wn * 64 + nf * 8;
                bf[nf][0] = Bs[kk + tg][nb + g];
                bf[nf][1] = Bs[kk + tg + 4][nb + g];
            }
#pragma unroll
            for (int mf = 0; mf < 2; ++mf)
#pragma unroll
                for (int nf = 0; nf < 8; ++nf)
                    mma_tf32(acc[mf][nf], af[mf], bf[nf]);
        }
    }

    if (MODE == 0) {
#pragma unroll
        for (int mf = 0; mf < 2; ++mf) {
            int row0 = m0 + wm * 32 + mf * 16 + g;
#pragma unroll
            for (int nf = 0; nf < 8; ++nf) {
                int col = n0 + wn * 64 + nf * 8 + tg * 2;
                float bv0 = bias[col];
                float bv1 = bias[col + 1];
                *(float2*)&C[(size_t)row0 * N + col] =
                    make_float2(acc[mf][nf][0] + bv0, acc[mf][nf][1] + bv1);
                *(float2*)&C[(size_t)(row0 + 8) * N + col] =
                    make_float2(acc[mf][nf][2] + bv0, acc[mf][nf][3] + bv1);
            }
        }
    } else {
        const int widx = wn * 4 + tg;
#pragma unroll
        for (int mf = 0; mf < 2; ++mf) {
            float p0 = 0.f, p1 = 0.f;
#pragma unroll
            for (int nf = 0; nf < 8; ++nf) {
                int col = n0 + wn * 64 + nf * 8 + tg * 2;
                float bv0 = bias[col];
                float bv1 = bias[col + 1];
                float w0 = w2[col];
                float w1 = w2[col + 1];
                p0 = fmaf(fast_tanh(acc[mf][nf][0] + bv0), w0, p0);
                p0 = fmaf(fast_tanh(acc[mf][nf][1] + bv1), w1, p0);
                p1 = fmaf(fast_tanh(acc[mf][nf][2] + bv0), w0, p1);
                p1 = fmaf(fast_tanh(acc[mf][nf][3] + bv1), w1, p1);
            }
            int r = wm * 32 + mf * 16 + g;
            red[r][widx] = p0;
            red[r + 8][widx] = p1;
        }
        __syncthreads();
        if (tid < 128) {
            float s = 0.f;
#pragma unroll
            for (int q = 0; q < 8; ++q) s += red[tid][q];
            spart[(size_t)ntile * M_ROWS + m0 + tid] = s;
        }
    }
}

__global__ void __launch_bounds__(256, 2) gemm_proj_kernel(const float* __restrict__ x) {
    gemm_tc_body<DD, NPROJ, 0>(x, g_Wcat, g_bcat, g_P, nullptr, nullptr);
}
__global__ void __launch_bounds__(256, 2) gemm_score_kernel(const float* __restrict__ W1,
                                                            const float* __restrict__ b1,
                                                            const float* __restrict__ w2) {
    gemm_tc_body<N2H, N2H, 1>(g_Hout, W1, b1, nullptr, w2, g_spart);
}

// ---------------- GRU: R7/R13 exact (frozen empirical optimum) ----------------
__device__ __forceinline__ void st_cluster_f32(uint32_t addr, uint32_t rank, float v) {
    uint32_t ra;
    asm volatile("mapa.shared::cluster.u32 %0, %1, %2;" : "=r"(ra) : "r"(addr), "r"(rank));
    asm volatile("st.shared::cluster.f32 [%0], %1;" :: "r"(ra), "f"(v) : "memory");
}

__global__ void __launch_bounds__(256, 2) __cluster_dims__(8, 1, 1)
gru_kernel(const float* __restrict__ Uzf, const float* __restrict__ Uhf,
           const float* __restrict__ Uzb, const float* __restrict__ Uhb) {
    __shared__ __align__(16) float sh[2][4][256];   // double-buffered h: [buf][batch][256 cols]
    __shared__ __align__(16) float pp[8][8][32];    // partials [ks][gate*4+batch][j]

    const int tid = threadIdx.x;
    uint32_t rank;
    asm("mov.u32 %0, %%cluster_ctarank;" : "=r"(rank));
    const int cid = blockIdx.x >> 3;
    const int dir = cid >> 4;
    const int b0 = (cid & 15) * 4;
    const int j0 = (int)rank * 32;
    const float* Uz = dir ? Uzb : Uzf;
    const float* Uh = dir ? Uhb : Uhf;

    const int ks = tid >> 5;        // k-slice 0..7 (k in [ks*32, +32))
    const int j  = tid & 31;        // owned column within rank slice
    const int fb = (tid >> 5) & 3;  // finalize batch (tid < 128)
    const int fj = tid & 31;        // finalize column
    const bool fin = tid < 128;

    // U slice into registers, k-paired: 16 u64 per gate
    u64 uzr[16], uhr[16];
#pragma unroll
    for (int q = 0; q < 16; ++q) {
        int k = ks * 32 + 2 * q;
        float z0 = Uz[(size_t)k * HH + j0 + j];
        float z1 = Uz[(size_t)(k + 1) * HH + j0 + j];
        float h0 = Uh[(size_t)k * HH + j0 + j];
        float h1 = Uh[(size_t)(k + 1) * HH + j0 + j];
        PACK2(uzr[q], z0, z1);
        PACK2(uhr[q], h0, h1);
    }

    const uint32_t sh_base = (uint32_t)__cvta_generic_to_shared(&sh[0][0][0]);
    const uint32_t hoff = (uint32_t)(fb * 256 + j0 + fj) * 4u;
    float hself = 0.f;

    asm volatile("barrier.cluster.arrive.aligned;" ::: "memory");
    asm volatile("barrier.cluster.wait.aligned;" ::: "memory");

    for (int t = 0; t < SS; ++t) {
        const int ts = dir ? (SS - 1 - t) : t;
        float xz = 0.f, xh = 0.f;
        if (fin) {
            const float* pr = &g_P[((size_t)(b0 + fb) * SS + ts) * NPROJ + dir * 512 + j0 + fj];
            xz = pr[0];
            xh = pr[HH];
        }

        if (t > 0) {
            const ulonglong2* hb = (const ulonglong2*)&sh[(t & 1) ^ 1][0][0];
            u64 az0 = 0, az1 = 0, az2 = 0, az3 = 0;
            u64 ah0 = 0, ah1 = 0, ah2 = 0, ah3 = 0;
#pragma unroll
            for (int i = 0; i < 8; ++i) {
                ulonglong2 h0 = hb[0 * 64 + ks * 8 + i];
                ulonglong2 h1 = hb[1 * 64 + ks * 8 + i];
                ulonglong2 h2 = hb[2 * 64 + ks * 8 + i];
                ulonglong2 h3 = hb[3 * 64 + ks * 8 + i];
                u64 uz0 = uzr[2 * i], uz1 = uzr[2 * i + 1];
                u64 uh0 = uhr[2 * i], uh1 = uhr[2 * i + 1];
                FMA2(az0, uz0, h0.x); FMA2(az0, uz1, h0.y);
                FMA2(az1, uz0, h1.x); FMA2(az1, uz1, h1.y);
                FMA2(az2, uz0, h2.x); FMA2(az2, uz1, h2.y);
                FMA2(az3, uz0, h3.x); FMA2(az3, uz1, h3.y);
                FMA2(ah0, uh0, h0.x); FMA2(ah0, uh1, h0.y);
                FMA2(ah1, uh0, h1.x); FMA2(ah1, uh1, h1.y);
                FMA2(ah2, uh0, h2.x); FMA2(ah2, uh1, h2.y);
                FMA2(ah3, uh0, h3.x); FMA2(ah3, uh1, h3.y);
            }
            float lo, hi;
            UNPACK2(lo, hi, az0); pp[ks][0][j] = lo + hi;
            UNPACK2(lo, hi, az1); pp[ks][1][j] = lo + hi;
            UNPACK2(lo, hi, az2); pp[ks][2][j] = lo + hi;
            UNPACK2(lo, hi, az3); pp[ks][3][j] = lo + hi;
            UNPACK2(lo, hi, ah0); pp[ks][4][j] = lo + hi;
            UNPACK2(lo, hi, ah1); pp[ks][5][j] = lo + hi;
            UNPACK2(lo, hi, ah2); pp[ks][6][j] = lo + hi;
            UNPACK2(lo, hi, ah3); pp[ks][7][j] = lo + hi;
        }
        __syncthreads();

        if (fin) {
            float az = xz, ah = xh;
            if (t > 0) {
#pragma unroll
                for (int s2 = 0; s2 < 8; ++s2) {
                    az += pp[s2][fb][fj];
                    ah += pp[s2][4 + fb][fj];
                }
            }
            float z = fast_sigmoid(az);
            float hc = fast_tanh(ah);
            float hnew = fmaf(z, hself - hc, hc);
            hself = hnew;

            uint32_t loff = sh_base + ((uint32_t)(t & 1) << 12) + hoff;
#pragma unroll
            for (uint32_t r = 0; r < 8; ++r) st_cluster_f32(loff, r, hnew);

            g_Hout[((size_t)(b0 + fb) * SS + ts) * N2H + dir * HH + j0 + fj] = hnew;
        }

        asm volatile("barrier.cluster.arrive.aligned;" ::: "memory");
        asm volatile("barrier.cluster.wait.aligned;" ::: "memory");
    }
}

// ---------------- softmax over S ----------------
__global__ void __launch_bounds__(256) softmax_kernel() {
    __shared__ float sp[SS];
    __shared__ float rbuf[256];
    const int b = blockIdx.x;
    const int tid = threadIdx.x;

    float mx = -1e30f;
    for (int i = tid; i < SS; i += 256) {
        int row = b * SS + i;
        float v = g_spart[row] + g_spart[M_ROWS + row] +
                  g_spart[2 * M_ROWS + row] + g_spart[3 * M_ROWS + row];
        sp[i] = v;
        mx = fmaxf(mx, v);
    }
    rbuf[tid] = mx;
    __syncthreads();
#pragma unroll
    for (int o = 128; o > 0; o >>= 1) {
        if (tid < o) rbuf[tid] = fmaxf(rbuf[tid], rbuf[tid + o]);
        __syncthreads();
    }
    float m = rbuf[0];
    __syncthreads();

    float sum = 0.f;
    for (int i = tid; i < SS; i += 256) {
        float e = __expf(sp[i] - m);
        sp[i] = e;
        sum += e;
    }
    rbuf[tid] = sum;
    __syncthreads();
#pragma unroll
    for (int o = 128; o > 0; o >>= 1) {
        if (tid < o) rbuf[tid] += rbuf[tid + o];
        __syncthreads();
    }
    float inv = __fdividef(1.f, rbuf[0]);
    __syncthreads();
    for (int i = tid; i < SS; i += 256) g_attn[b * SS + i] = sp[i] * inv;
}

// ---------------- context ----------------
__global__ void __launch_bounds__(256) ctx_partial_kernel() {
    const int b = blockIdx.x;
    const int ch = blockIdx.y;
    const int tid = threadIdx.x;
    const float* hb = &g_Hout[((size_t)b * SS + ch * 128) * N2H];
    const float* ap = &g_attn[b * SS + ch * 128];
    float c0 = 0.f, c1 = 0.f;
    for (int s = 0; s < 128; ++s) {
        float p = ap[s];
        c0 = fmaf(p, hb[(size_t)s * N2H + tid], c0);
        c1 = fmaf(p, hb[(size_t)s * N2H + HH + tid], c1);
    }
    g_cpart[((size_t)ch * BB + b) * N2H + tid] = c0;
    g_cpart[((size_t)ch * BB + b) * N2H + HH + tid] = c1;
}

__global__ void __launch_bounds__(512) ctx_final_kernel(float* __restrict__ out) {
    const int b = blockIdx.x;
    const int tid = threadIdx.x;
    float s = 0.f;
#pragma unroll
    for (int ch = 0; ch < 8; ++ch)
        s += g_cpart[((size_t)ch * BB + b) * N2H + tid];
    out[b * N2H + tid] = s;
}

// ---------------- launcher ----------------
extern "C" void kernel_launch(void* const* d_in, const int* in_sizes, int n_in,
                              void* d_out, int out_size) {
    const float* x   = (const float*)d_in[0];
    const float* Wzf = (const float*)d_in[1];
    const float* Uzf = (const float*)d_in[2];
    const float* bzf = (const float*)d_in[3];
    const float* Whf = (const float*)d_in[4];
    const float* Uhf = (const float*)d_in[5];
    const float* bhf = (const float*)d_in[6];
    const float* Wzb = (const float*)d_in[7];
    const float* Uzb = (const float*)d_in[8];
    const float* bzb = (const float*)d_in[9];
    const float* Whb = (const float*)d_in[10];
    const float* Uhb = (const float*)d_in[11];
    const float* bhb = (const float*)d_in[12];
    const float* W1  = (const float*)d_in[13];
    const float* b1  = (const float*)d_in[14];
    const float* w2  = (const float*)d_in[15];
    float* out = (float*)d_out;

    pack_weights<<<512, 256>>>(Wzf, Whf, Wzb, Whb, bzf, bhf, bzb, bhb);
    // n-tile fastest (blockIdx.x) so CTAs sharing an A block are adjacent -> L2 reuse
    gemm_proj_kernel<<<dim3(NPROJ / 128, M_ROWS / 128), 256>>>(x);
    gru_kernel<<<256, 256>>>(Uzf, Uhf, Uzb, Uhb);
    gemm_score_kernel<<<dim3(N2H / 128, M_ROWS / 128), 256>>>(W1, b1, w2);
    softmax_kernel<<<BB, 256>>>();
    ctx_partial_kernel<<<dim3(BB, 8), 256>>>();
    ctx_final_kernel<<<BB, 512>>>(out);
}

// round 17
// speedup vs baseline: 1.6085x; 1.6085x over previous
#include <cuda_runtime.h>
#include <math.h>
#include <stdint.h>

#define BB   64
#define SS   1024
#define DD   128
#define HH   256
#define M_ROWS (BB*SS)          // 65536
#define NPROJ  (4*HH)           // 1024
#define N2H    (2*HH)           // 512

typedef unsigned long long u64;

// ---------------- device scratch ----------------
__device__ __align__(16) float g_P[(size_t)M_ROWS * NPROJ];
__device__ __align__(16) float g_Hout[(size_t)M_ROWS * N2H];
__device__ __align__(16) float g_spart[4 * M_ROWS];
__device__ __align__(16) float g_attn[M_ROWS];
__device__ __align__(16) float g_cpart[8 * BB * N2H];

// ---------------- helpers ----------------
#define FMA2(d, a, b) asm("fma.rn.f32x2 %0, %1, %2, %0;" : "+l"(d) : "l"(a), "l"(b))
#define PACK2(d, lo, hi) asm("mov.b64 %0, {%1, %2};" : "=l"(d) : "f"(lo), "f"(hi))
#define UNPACK2(lo, hi, d) asm("mov.b64 {%0, %1}, %2;" : "=f"(lo), "=f"(hi) : "l"(d))

__device__ __forceinline__ float fast_sigmoid(float x) {
    return __fdividef(1.f, 1.f + __expf(-x));
}
__device__ __forceinline__ float fast_tanh(float x) {
    return 1.f - __fdividef(2.f, __expf(2.f * x) + 1.f);
}
__device__ __forceinline__ uint32_t to_tf32(float f) {
    uint32_t u;
    asm("cvt.rna.tf32.f32 %0, %1;" : "=r"(u) : "f"(f));
    return u;
}
__device__ __forceinline__ void mma_tf32(float* d, const uint32_t* a, const uint32_t* b) {
    asm volatile("mma.sync.aligned.m16n8k8.row.col.f32.tf32.tf32.f32 "
                 "{%0,%1,%2,%3}, {%4,%5,%6,%7}, {%8,%9}, {%0,%1,%2,%3};"
                 : "+f"(d[0]), "+f"(d[1]), "+f"(d[2]), "+f"(d[3])
                 : "r"(a[0]), "r"(a[1]), "r"(a[2]), "r"(a[3]), "r"(b[0]), "r"(b[1]));
}

// ---------------- tf32 tensor-core GEMM (R13-exact math, stride 132) ----------------
// B is addressed with row stride BN and column base bcol (lets the proj kernel
// read the raw W matrices directly -> no pack_weights pass). biasT/w2T are
// pre-offset to the tile's column base. blockIdx.x = n-tile (fastest, L2 A-reuse).
template<int K, int N, int BN, int MODE>
__device__ __forceinline__ void gemm_tc_body(const float* __restrict__ A, const float* __restrict__ B,
                                             int bcol, const float* __restrict__ biasT,
                                             float* __restrict__ C,
                                             const float* __restrict__ w2T, float* __restrict__ spart) {
    __shared__ __align__(16) uint32_t As[16][132];
    __shared__ __align__(16) uint32_t Bs[16][132];
    __shared__ float red[128][9];

    const int tid = threadIdx.x;
    const int ntile = blockIdx.x;
    const int m0 = blockIdx.y * 128;
    const int n0 = ntile * 128;
    const int warp = tid >> 5;
    const int lane = tid & 31;
    const int wm = warp & 3;
    const int wn = warp >> 2;
    const int g  = lane >> 2;
    const int tg = lane & 3;

    const int arow = tid >> 2;
    const int akq  = (tid & 3) * 4;
    const int bkr  = tid >> 5;
    const int bnq  = (tid & 31) * 4;

    float acc[2][8][4];
#pragma unroll
    for (int mf = 0; mf < 2; ++mf)
#pragma unroll
        for (int nf = 0; nf < 8; ++nf)
#pragma unroll
            for (int q = 0; q < 4; ++q) acc[mf][nf][q] = 0.f;

    const int NC = K / 16;
    float4 a0s = *(const float4*)&A[(size_t)(m0 + arow) * K + akq];
    float4 a1s = *(const float4*)&A[(size_t)(m0 + arow + 64) * K + akq];
    float4 b0s = *(const float4*)&B[(size_t)bkr * BN + bcol + bnq];
    float4 b1s = *(const float4*)&B[(size_t)(bkr + 8) * BN + bcol + bnq];

    for (int c = 0; c < NC; ++c) {
        __syncthreads();
        As[akq + 0][arow] = to_tf32(a0s.x);
        As[akq + 1][arow] = to_tf32(a0s.y);
        As[akq + 2][arow] = to_tf32(a0s.z);
        As[akq + 3][arow] = to_tf32(a0s.w);
        As[akq + 0][arow + 64] = to_tf32(a1s.x);
        As[akq + 1][arow + 64] = to_tf32(a1s.y);
        As[akq + 2][arow + 64] = to_tf32(a1s.z);
        As[akq + 3][arow + 64] = to_tf32(a1s.w);
        {
            uint4 v0 = make_uint4(to_tf32(b0s.x), to_tf32(b0s.y), to_tf32(b0s.z), to_tf32(b0s.w));
            uint4 v1 = make_uint4(to_tf32(b1s.x), to_tf32(b1s.y), to_tf32(b1s.z), to_tf32(b1s.w));
            *(uint4*)&Bs[bkr][bnq] = v0;
            *(uint4*)&Bs[bkr + 8][bnq] = v1;
        }
        if (c + 1 < NC) {
            int kb = (c + 1) * 16;
            a0s = *(const float4*)&A[(size_t)(m0 + arow) * K + kb + akq];
            a1s = *(const float4*)&A[(size_t)(m0 + arow + 64) * K + kb + akq];
            b0s = *(const float4*)&B[(size_t)(kb + bkr) * BN + bcol + bnq];
            b1s = *(const float4*)&B[(size_t)(kb + bkr + 8) * BN + bcol + bnq];
        }
        __syncthreads();
#pragma unroll
        for (int kk = 0; kk < 16; kk += 8) {
            uint32_t af[2][4];
#pragma unroll
            for (int mf = 0; mf < 2; ++mf) {
                int mb = wm * 32 + mf * 16;
                af[mf][0] = As[kk + tg][mb + g];
                af[mf][1] = As[kk + tg][mb + g + 8];
                af[mf][2] = As[kk + tg + 4][mb + g];
                af[mf][3] = As[kk + tg + 4][mb + g + 8];
            }
            uint32_t bf[8][2];
#pragma unroll
            for (int nf = 0; nf < 8; ++nf) {
                int nb = wn * 64 + nf * 8;
                bf[nf][0] = Bs[kk + tg][nb + g];
                bf[nf][1] = Bs[kk + tg + 4][nb + g];
            }
#pragma unroll
            for (int mf = 0; mf < 2; ++mf)
#pragma unroll
                for (int nf = 0; nf < 8; ++nf)
                    mma_tf32(acc[mf][nf], af[mf], bf[nf]);
        }
    }

    if (MODE == 0) {
#pragma unroll
        for (int mf = 0; mf < 2; ++mf) {
            int row0 = m0 + wm * 32 + mf * 16 + g;
#pragma unroll
            for (int nf = 0; nf < 8; ++nf) {
                int lc = wn * 64 + nf * 8 + tg * 2;    // local column in tile
                float bv0 = biasT[lc];
                float bv1 = biasT[lc + 1];
                *(float2*)&C[(size_t)row0 * N + n0 + lc] =
                    make_float2(acc[mf][nf][0] + bv0, acc[mf][nf][1] + bv1);
                *(float2*)&C[(size_t)(row0 + 8) * N + n0 + lc] =
                    make_float2(acc[mf][nf][2] + bv0, acc[mf][nf][3] + bv1);
            }
        }
    } else {
        const int widx = wn * 4 + tg;
#pragma unroll
        for (int mf = 0; mf < 2; ++mf) {
            float p0 = 0.f, p1 = 0.f;
#pragma unroll
            for (int nf = 0; nf < 8; ++nf) {
                int lc = wn * 64 + nf * 8 + tg * 2;
                float bv0 = biasT[lc];
                float bv1 = biasT[lc + 1];
                float w0 = w2T[lc];
                float w1 = w2T[lc + 1];
                p0 = fmaf(fast_tanh(acc[mf][nf][0] + bv0), w0, p0);
                p0 = fmaf(fast_tanh(acc[mf][nf][1] + bv1), w1, p0);
                p1 = fmaf(fast_tanh(acc[mf][nf][2] + bv0), w0, p1);
                p1 = fmaf(fast_tanh(acc[mf][nf][3] + bv1), w1, p1);
            }
            int r = wm * 32 + mf * 16 + g;
            red[r][widx] = p0;
            red[r + 8][widx] = p1;
        }
        __syncthreads();
        if (tid < 128) {
            float s = 0.f;
#pragma unroll
            for (int q = 0; q < 8; ++q) s += red[tid][q];
            spart[(size_t)ntile * M_ROWS + m0 + tid] = s;
        }
    }
}

// Projection GEMM reading raw W matrices directly (no pack pass).
// n-tile sel: [0,256)=Wzf, [256,512)=Whf, [512,768)=Wzb, [768,1024)=Whb —
// matches the g_P column layout the GRU expects (dir*512 + {0:xz, 256:xh}).
__global__ void __launch_bounds__(256, 2) gemm_proj_kernel(
        const float* __restrict__ x,
        const float* __restrict__ Wzf, const float* __restrict__ Whf,
        const float* __restrict__ Wzb, const float* __restrict__ Whb,
        const float* __restrict__ bzf, const float* __restrict__ bhf,
        const float* __restrict__ bzb, const float* __restrict__ bhb) {
    const int n0 = blockIdx.x * 128;
    const int sel = n0 >> 8;
    const int cb = n0 & 255;
    const float* W = (sel == 0) ? Wzf : (sel == 1) ? Whf : (sel == 2) ? Wzb : Whb;
    const float* bb = (sel == 0) ? bzf : (sel == 1) ? bhf : (sel == 2) ? bzb : bhb;
    gemm_tc_body<DD, NPROJ, HH, 0>(x, W, cb, bb + cb, g_P, nullptr, nullptr);
}

__global__ void __launch_bounds__(256, 2) gemm_score_kernel(const float* __restrict__ W1,
                                                            const float* __restrict__ b1,
                                                            const float* __restrict__ w2) {
    const int n0 = blockIdx.x * 128;
    gemm_tc_body<N2H, N2H, N2H, 1>(g_Hout, W1, n0, b1 + n0, nullptr, w2 + n0, g_spart);
}

// ---------------- GRU: R7/R13 exact (frozen empirical optimum) ----------------
__device__ __forceinline__ void st_cluster_f32(uint32_t addr, uint32_t rank, float v) {
    uint32_t ra;
    asm volatile("mapa.shared::cluster.u32 %0, %1, %2;" : "=r"(ra) : "r"(addr), "r"(rank));
    asm volatile("st.shared::cluster.f32 [%0], %1;" :: "r"(ra), "f"(v) : "memory");
}

__global__ void __launch_bounds__(256, 2) __cluster_dims__(8, 1, 1)
gru_kernel(const float* __restrict__ Uzf, const float* __restrict__ Uhf,
           const float* __restrict__ Uzb, const float* __restrict__ Uhb) {
    __shared__ __align__(16) float sh[2][4][256];   // double-buffered h: [buf][batch][256 cols]
    __shared__ __align__(16) float pp[8][8][32];    // partials [ks][gate*4+batch][j]

    const int tid = threadIdx.x;
    uint32_t rank;
    asm("mov.u32 %0, %%cluster_ctarank;" : "=r"(rank));
    const int cid = blockIdx.x >> 3;
    const int dir = cid >> 4;
    const int b0 = (cid & 15) * 4;
    const int j0 = (int)rank * 32;
    const float* Uz = dir ? Uzb : Uzf;
    const float* Uh = dir ? Uhb : Uhf;

    const int ks = tid >> 5;        // k-slice 0..7 (k in [ks*32, +32))
    const int j  = tid & 31;        // owned column within rank slice
    const int fb = (tid >> 5) & 3;  // finalize batch (tid < 128)
    const int fj = tid & 31;        // finalize column
    const bool fin = tid < 128;

    // U slice into registers, k-paired: 16 u64 per gate
    u64 uzr[16], uhr[16];
#pragma unroll
    for (int q = 0; q < 16; ++q) {
        int k = ks * 32 + 2 * q;
        float z0 = Uz[(size_t)k * HH + j0 + j];
        float z1 = Uz[(size_t)(k + 1) * HH + j0 + j];
        float h0 = Uh[(size_t)k * HH + j0 + j];
        float h1 = Uh[(size_t)(k + 1) * HH + j0 + j];
        PACK2(uzr[q], z0, z1);
        PACK2(uhr[q], h0, h1);
    }

    const uint32_t sh_base = (uint32_t)__cvta_generic_to_shared(&sh[0][0][0]);
    const uint32_t hoff = (uint32_t)(fb * 256 + j0 + fj) * 4u;
    float hself = 0.f;

    asm volatile("barrier.cluster.arrive.aligned;" ::: "memory");
    asm volatile("barrier.cluster.wait.aligned;" ::: "memory");

    for (int t = 0; t < SS; ++t) {
        const int ts = dir ? (SS - 1 - t) : t;
        float xz = 0.f, xh = 0.f;
        if (fin) {
            const float* pr = &g_P[((size_t)(b0 + fb) * SS + ts) * NPROJ + dir * 512 + j0 + fj];
            xz = pr[0];
            xh = pr[HH];
        }

        if (t > 0) {
            const ulonglong2* hb = (const ulonglong2*)&sh[(t & 1) ^ 1][0][0];
            u64 az0 = 0, az1 = 0, az2 = 0, az3 = 0;
            u64 ah0 = 0, ah1 = 0, ah2 = 0, ah3 = 0;
#pragma unroll
            for (int i = 0; i < 8; ++i) {
                ulonglong2 h0 = hb[0 * 64 + ks * 8 + i];
                ulonglong2 h1 = hb[1 * 64 + ks * 8 + i];
                ulonglong2 h2 = hb[2 * 64 + ks * 8 + i];
                ulonglong2 h3 = hb[3 * 64 + ks * 8 + i];
                u64 uz0 = uzr[2 * i], uz1 = uzr[2 * i + 1];
                u64 uh0 = uhr[2 * i], uh1 = uhr[2 * i + 1];
                FMA2(az0, uz0, h0.x); FMA2(az0, uz1, h0.y);
                FMA2(az1, uz0, h1.x); FMA2(az1, uz1, h1.y);
                FMA2(az2, uz0, h2.x); FMA2(az2, uz1, h2.y);
                FMA2(az3, uz0, h3.x); FMA2(az3, uz1, h3.y);
                FMA2(ah0, uh0, h0.x); FMA2(ah0, uh1, h0.y);
                FMA2(ah1, uh0, h1.x); FMA2(ah1, uh1, h1.y);
                FMA2(ah2, uh0, h2.x); FMA2(ah2, uh1, h2.y);
                FMA2(ah3, uh0, h3.x); FMA2(ah3, uh1, h3.y);
            }
            float lo, hi;
            UNPACK2(lo, hi, az0); pp[ks][0][j] = lo + hi;
            UNPACK2(lo, hi, az1); pp[ks][1][j] = lo + hi;
            UNPACK2(lo, hi, az2); pp[ks][2][j] = lo + hi;
            UNPACK2(lo, hi, az3); pp[ks][3][j] = lo + hi;
            UNPACK2(lo, hi, ah0); pp[ks][4][j] = lo + hi;
            UNPACK2(lo, hi, ah1); pp[ks][5][j] = lo + hi;
            UNPACK2(lo, hi, ah2); pp[ks][6][j] = lo + hi;
            UNPACK2(lo, hi, ah3); pp[ks][7][j] = lo + hi;
        }
        __syncthreads();

        if (fin) {
            float az = xz, ah = xh;
            if (t > 0) {
#pragma unroll
                for (int s2 = 0; s2 < 8; ++s2) {
                    az += pp[s2][fb][fj];
                    ah += pp[s2][4 + fb][fj];
                }
            }
            float z = fast_sigmoid(az);
            float hc = fast_tanh(ah);
            float hnew = fmaf(z, hself - hc, hc);
            hself = hnew;

            uint32_t loff = sh_base + ((uint32_t)(t & 1) << 12) + hoff;
#pragma unroll
            for (uint32_t r = 0; r < 8; ++r) st_cluster_f32(loff, r, hnew);

            g_Hout[((size_t)(b0 + fb) * SS + ts) * N2H + dir * HH + j0 + fj] = hnew;
        }

        asm volatile("barrier.cluster.arrive.aligned;" ::: "memory");
        asm volatile("barrier.cluster.wait.aligned;" ::: "memory");
    }
}

// ---------------- softmax over S ----------------
__global__ void __launch_bounds__(256) softmax_kernel() {
    __shared__ float sp[SS];
    __shared__ float rbuf[256];
    const int b = blockIdx.x;
    const int tid = threadIdx.x;

    float mx = -1e30f;
    for (int i = tid; i < SS; i += 256) {
        int row = b * SS + i;
        float v = g_spart[row] + g_spart[M_ROWS + row] +
                  g_spart[2 * M_ROWS + row] + g_spart[3 * M_ROWS + row];
        sp[i] = v;
        mx = fmaxf(mx, v);
    }
    rbuf[tid] = mx;
    __syncthreads();
#pragma unroll
    for (int o = 128; o > 0; o >>= 1) {
        if (tid < o) rbuf[tid] = fmaxf(rbuf[tid], rbuf[tid + o]);
        __syncthreads();
    }
    float m = rbuf[0];
    __syncthreads();

    float sum = 0.f;
    for (int i = tid; i < SS; i += 256) {
        float e = __expf(sp[i] - m);
        sp[i] = e;
        sum += e;
    }
    rbuf[tid] = sum;
    __syncthreads();
#pragma unroll
    for (int o = 128; o > 0; o >>= 1) {
        if (tid < o) rbuf[tid] += rbuf[tid + o];
        __syncthreads();
    }
    float inv = __fdividef(1.f, rbuf[0]);
    __syncthreads();
    for (int i = tid; i < SS; i += 256) g_attn[b * SS + i] = sp[i] * inv;
}

// ---------------- context ----------------
__global__ void __launch_bounds__(256) ctx_partial_kernel() {
    const int b = blockIdx.x;
    const int ch = blockIdx.y;
    const int tid = threadIdx.x;
    const float* hb = &g_Hout[((size_t)b * SS + ch * 128) * N2H];
    const float* ap = &g_attn[b * SS + ch * 128];
    float c0 = 0.f, c1 = 0.f;
    for (int s = 0; s < 128; ++s) {
        float p = ap[s];
        c0 = fmaf(p, hb[(size_t)s * N2H + tid], c0);
        c1 = fmaf(p, hb[(size_t)s * N2H + HH + tid], c1);
    }
    g_cpart[((size_t)ch * BB + b) * N2H + tid] = c0;
    g_cpart[((size_t)ch * BB + b) * N2H + HH + tid] = c1;
}

__global__ void __launch_bounds__(512) ctx_final_kernel(float* __restrict__ out) {
    const int b = blockIdx.x;
    const int tid = threadIdx.x;
    float s = 0.f;
#pragma unroll
    for (int ch = 0; ch < 8; ++ch)
        s += g_cpart[((size_t)ch * BB + b) * N2H + tid];
    out[b * N2H + tid] = s;
}

// ---------------- launcher ----------------
extern "C" void kernel_launch(void* const* d_in, const int* in_sizes, int n_in,
                              void* d_out, int out_size) {
    const float* x   = (const float*)d_in[0];
    const float* Wzf = (const float*)d_in[1];
    const float* Uzf = (const float*)d_in[2];
    const float* bzf = (const float*)d_in[3];
    const float* Whf = (const float*)d_in[4];
    const float* Uhf = (const float*)d_in[5];
    const float* bhf = (const float*)d_in[6];
    const float* Wzb = (const float*)d_in[7];
    const float* Uzb = (const float*)d_in[8];
    const float* bzb = (const float*)d_in[9];
    const float* Whb = (const float*)d_in[10];
    const float* Uhb = (const float*)d_in[11];
    const float* bhb = (const float*)d_in[12];
    const float* W1  = (const float*)d_in[13];
    const float* b1  = (const float*)d_in[14];
    const float* w2  = (const float*)d_in[15];
    float* out = (float*)d_out;

    // proj reads raw W matrices directly (pack_weights eliminated)
    gemm_proj_kernel<<<dim3(NPROJ / 128, M_ROWS / 128), 256>>>(
        x, Wzf, Whf, Wzb, Whb, bzf, bhf, bzb, bhb);
    gru_kernel<<<256, 256>>>(Uzf, Uhf, Uzb, Uhb);
    gemm_score_kernel<<<dim3(N2H / 128, M_ROWS / 128), 256>>>(W1, b1, w2);
    softmax_kernel<<<BB, 256>>>();
    ctx_partial_kernel<<<dim3(BB, 8), 256>>>();
    ctx_final_kernel<<<BB, 512>>>(out);
}